// round 2
// baseline (speedup 1.0000x reference)
#include <cuda_runtime.h>
#include <math.h>

#define H      1024
#define L      512
#define G4     4096      // 4H gate rows
#define KIN    4096      // concat(x,hi) feature dim
#define FIVEH  5120
#define LABELS 122
#define NBLK   128       // persistent LSTM blocks
#define NTHR   1024

// ---- static device scratch (allocation-free rule) ----
__device__ float g_Wrec[G4 * H];        // 16 MB: W_ih[:,4096:] + W_hh
__device__ float g_bias[G4];
__device__ float g_P[L * G4];           // 8 MB: precomputed input gates + bias
__device__ float g_outs[L * H];         // 2 MB: h_t for all steps (also broadcast medium)
__device__ int   g_flags[L * NBLK];     // per (step, block) publish counters

// ---- packed fp32x2 FMA (Blackwell f32x2 pipe) ----
__device__ __forceinline__ void fma2(float2& d, const float2& a, const float2& b) {
    unsigned long long dd = *reinterpret_cast<const unsigned long long*>(&d);
    unsigned long long aa = *reinterpret_cast<const unsigned long long*>(&a);
    unsigned long long bb = *reinterpret_cast<const unsigned long long*>(&b);
    asm("fma.rn.f32x2 %0, %1, %2, %0;" : "+l"(dd) : "l"(aa), "l"(bb));
    d = *reinterpret_cast<float2*>(&dd);
}

__device__ __forceinline__ float sigm(float x) { return 1.f / (1.f + __expf(-x)); }

// ============================================================
// Kernel 1: build W_rec, bias, zero flags
// ============================================================
__global__ void prep_kernel(const float* __restrict__ W_ih, const float* __restrict__ W_hh,
                            const float* __restrict__ b_ih, const float* __restrict__ b_hh) {
    int idx = blockIdx.x * blockDim.x + threadIdx.x;
    if (idx < G4 * H) {
        int r = idx >> 10, j = idx & 1023;
        g_Wrec[idx] = W_ih[r * FIVEH + KIN + j] + W_hh[idx];
    }
    if (idx < G4) g_bias[idx] = b_ih[idx] + b_hh[idx];
    if (idx < L * NBLK) g_flags[idx] = 0;
}

// ============================================================
// Kernel 2: P[m][n] = sum_k feats[m][k] * W_ih[n][k] + bias[n]
// 128x128 tile, 8x8 microtile (n packed as float2), BK=8, 256 thr
// ============================================================
#define BM 128
#define BN 128
#define BKK 8

__global__ __launch_bounds__(256) void gemm_kernel(const float* __restrict__ x,
                                                   const float* __restrict__ hi,
                                                   const float* __restrict__ W_ih) {
    __shared__ float As[BKK][BM];
    __shared__ float Bs[BKK][BN];
    int tid = threadIdx.x;
    int bm = blockIdx.y, bn = blockIdx.x;
    int rowl = tid >> 1;                 // 0..127 (both A-row and B-row loader index)
    int koff = (tid & 1) * 4;            // 0 or 4
    int m = bm * BM + rowl;
    int n = bn * BN + rowl;
    int tr = tid >> 4, tcx = tid & 15;   // 16x16 thread grid, 8(m) x 8(n) microtile

    float2 acc[8][4];
#pragma unroll
    for (int i = 0; i < 8; i++)
#pragma unroll
        for (int j = 0; j < 4; j++) acc[i][j] = make_float2(0.f, 0.f);

    for (int k0 = 0; k0 < KIN; k0 += BKK) {
        int ka = k0 + koff;
        const float* asrc = (ka < 2048) ? (x + m * 2048 + ka) : (hi + m * 2048 + (ka - 2048));
        float4 av = *(const float4*)asrc;
        float4 bv = *(const float4*)(W_ih + n * FIVEH + ka);
        __syncthreads();
        As[koff + 0][rowl] = av.x; As[koff + 1][rowl] = av.y;
        As[koff + 2][rowl] = av.z; As[koff + 3][rowl] = av.w;
        Bs[koff + 0][rowl] = bv.x; Bs[koff + 1][rowl] = bv.y;
        Bs[koff + 2][rowl] = bv.z; Bs[koff + 3][rowl] = bv.w;
        __syncthreads();
#pragma unroll
        for (int kk = 0; kk < BKK; kk++) {
            float a[8];
            float2 b2[4];
            *(float4*)&a[0] = *(float4*)&As[kk][tr * 8];
            *(float4*)&a[4] = *(float4*)&As[kk][tr * 8 + 4];
            *(float4*)&b2[0] = *(float4*)&Bs[kk][tcx * 8];
            *(float4*)&b2[2] = *(float4*)&Bs[kk][tcx * 8 + 4];
#pragma unroll
            for (int i = 0; i < 8; i++) {
                float2 aa = make_float2(a[i], a[i]);
#pragma unroll
                for (int j = 0; j < 4; j++) fma2(acc[i][j], aa, b2[j]);
            }
        }
    }
    int nbase = bn * BN + tcx * 8;
    float2 bias2[4];
#pragma unroll
    for (int j = 0; j < 4; j++) bias2[j] = *(const float2*)&g_bias[nbase + 2 * j];
#pragma unroll
    for (int i = 0; i < 8; i++) {
        int mrow = bm * BM + tr * 8 + i;
        float2* dst = (float2*)&g_P[mrow * G4 + nbase];
#pragma unroll
        for (int j = 0; j < 4; j++) {
            float2 v = acc[i][j];
            v.x += bias2[j].x; v.y += bias2[j].y;
            dst[j] = v;
        }
    }
}

// ============================================================
// Kernel 3: persistent LSTM recurrence.
// Block b owns h indices [b*8, b*8+8) -> 32 gate rows, W_rec slice
// register-resident (32 floats/thread). Per step: f32x2 matvec,
// warp butterflies, smem cross-chunk reduce, warp0 does gates +
// publishes h slice to g_outs + flag; all blocks poll flags, reload h.
// ============================================================
__global__ __launch_bounds__(NTHR, 1) void lstm_kernel() {
    __shared__ float h_sh[H];
    __shared__ float red[32][4];

    int tid = threadIdx.x, b = blockIdx.x;
    int w = tid >> 5, l = tid & 31;
    int rg = w >> 2;          // row group: 4 rows rr = rg*4..rg*4+3
    int cc = w & 3;           // col chunk: cols [cc*256, cc*256+256)
    int jbase = b * 8;

    // load register-resident weights: wreg[row][i] covers cols cc*256 + i*64 + 2l (+1)
    float2 wreg[4][4];
#pragma unroll
    for (int row = 0; row < 4; row++) {
        int rr = rg * 4 + row;
        int r = (rr >> 3) * 1024 + jbase + (rr & 7);
        const float2* wp = (const float2*)(g_Wrec + r * H + cc * 256);
#pragma unroll
        for (int i = 0; i < 4; i++) wreg[row][i] = wp[i * 32 + l];
    }
    h_sh[tid] = 0.f;
    float c_reg = 0.f;                                  // used by warp0 lanes 0..7
    int prow = (l >> 3) * 1024 + jbase + (l & 7);       // warp0: P row per lane
    __syncthreads();

    volatile int* vflags = (volatile int*)g_flags;

    for (int t = 0; t < L; t++) {
        float pval = 0.f;
        if (w == 0) pval = g_P[t * G4 + prow];          // latency hidden under FMAs

        // --- matvec slice: 16 f32x2 FMA + 4 LDS.64 per thread ---
        float2 acc[4];
#pragma unroll
        for (int row = 0; row < 4; row++) acc[row] = make_float2(0.f, 0.f);
        const float2* h2 = (const float2*)h_sh;
#pragma unroll
        for (int i = 0; i < 4; i++) {
            float2 hv = h2[cc * 128 + i * 32 + l];
#pragma unroll
            for (int row = 0; row < 4; row++) fma2(acc[row], wreg[row][i], hv);
        }
        float accs[4];
#pragma unroll
        for (int row = 0; row < 4; row++) accs[row] = acc[row].x + acc[row].y;
#pragma unroll
        for (int off = 16; off; off >>= 1)
#pragma unroll
            for (int row = 0; row < 4; row++)
                accs[row] += __shfl_xor_sync(0xffffffffu, accs[row], off);
        if (l == 0) {
#pragma unroll
            for (int row = 0; row < 4; row++) red[rg * 4 + row][cc] = accs[row];
        }
        __syncthreads();

        // --- warp0: final sum, gate nonlinearities, publish h slice ---
        if (w == 0) {
            float gate = pval + red[l][0] + red[l][1] + red[l][2] + red[l][3];
            float fg = __shfl_sync(0xffffffffu, gate, l + 8);
            float gg = __shfl_sync(0xffffffffu, gate, l + 16);
            float og = __shfl_sync(0xffffffffu, gate, l + 24);
            if (l < 8) {
                float cn = sigm(fg) * c_reg + sigm(gate) * tanhf(gg);
                float hn = sigm(og) * tanhf(cn);
                c_reg = cn;
                g_outs[t * H + jbase + l] = hn;
                __threadfence();
                atomicAdd(&g_flags[t * NBLK + b], 1);   // release per publishing lane
            }
        }

        // --- wait for all blocks' h_t, reload into smem ---
        if (t < L - 1) {
            if (tid < NBLK) {
                while (vflags[t * NBLK + tid] < 8) { }
                __threadfence();
            }
            __syncthreads();
            h_sh[tid] = __ldcg(&g_outs[t * H + tid]);
            __syncthreads();
        }
    }
}

// ============================================================
// Kernel 4: out[t][lab] = outs[t] . W_fc[lab] + b_fc[lab]
// ============================================================
__global__ __launch_bounds__(256) void fc_kernel(const float* __restrict__ W_fc,
                                                 const float* __restrict__ b_fc,
                                                 float* __restrict__ out) {
    int t = blockIdx.x;
    __shared__ float hsh[H];
    for (int k = threadIdx.x; k < H; k += 256) hsh[k] = g_outs[t * H + k];
    __syncthreads();
    int w = threadIdx.x >> 5, l = threadIdx.x & 31;
    for (int lab = w; lab < LABELS; lab += 8) {
        const float* wr = W_fc + lab * H;
        float s = 0.f;
#pragma unroll 8
        for (int k = l; k < H; k += 32) s += wr[k] * hsh[k];
#pragma unroll
        for (int off = 16; off; off >>= 1) s += __shfl_xor_sync(0xffffffffu, s, off);
        if (l == 0) out[t * LABELS + lab] = s + b_fc[lab];
    }
}

// ============================================================
extern "C" void kernel_launch(void* const* d_in, const int* in_sizes, int n_in,
                              void* d_out, int out_size) {
    const float* x    = (const float*)d_in[0];
    const float* hi   = (const float*)d_in[1];
    const float* W_ih = (const float*)d_in[2];
    const float* W_hh = (const float*)d_in[3];
    const float* b_ih = (const float*)d_in[4];
    const float* b_hh = (const float*)d_in[5];
    const float* W_fc = (const float*)d_in[6];
    const float* b_fc = (const float*)d_in[7];
    float* out = (float*)d_out;

    prep_kernel<<<(G4 * H + 255) / 256, 256>>>(W_ih, W_hh, b_ih, b_hh);
    gemm_kernel<<<dim3(KIN / BN, L / BM), 256>>>(x, hi, W_ih);
    lstm_kernel<<<NBLK, NTHR>>>();
    fc_kernel<<<L, 256>>>(W_fc, b_fc, out);
}

// round 6
// speedup vs baseline: 1.4919x; 1.4919x over previous
#include <cuda_runtime.h>
#include <cuda_bf16.h>
#include <cstdint>
#include <math.h>

#define H      1024
#define L      512
#define G4     4096
#define KIN    4096
#define FIVEH  5120
#define LABELS 122
#define NBLK   128
#define NTHR   1024

// ---- static device scratch ----
__device__ float g_Wrec[G4 * H];                 // 16 MB
__device__ float g_bias[G4];
__device__ float g_P[L * G4];                    // 8 MB
__device__ float g_outs[L * H];                  // 2 MB
__device__ int   g_flagw[NBLK];
__device__ __nv_bfloat16 g_W_hi[G4 * KIN];       // 32 MB
__device__ __nv_bfloat16 g_W_lo[G4 * KIN];       // 32 MB
__device__ __nv_bfloat16 g_F_hi[L * KIN];        // 4 MB
__device__ __nv_bfloat16 g_F_lo[L * KIN];        // 4 MB

// ============ PTX helpers (plain sm_80+ features only) ============
__device__ __forceinline__ uint32_t smem_u32(const void* p) {
    uint32_t a;
    asm("{ .reg .u64 t; cvta.to.shared.u64 t, %1; cvt.u32.u64 %0, t; }" : "=r"(a) : "l"(p));
    return a;
}
#define CP_ASYNC16(dst, src) \
    asm volatile("cp.async.cg.shared.global [%0], [%1], 16;" :: "r"(dst), "l"(src))
#define CP_COMMIT() asm volatile("cp.async.commit_group;" ::: "memory")
#define CP_WAIT(n)  asm volatile("cp.async.wait_group %0;" :: "n"(n) : "memory")

__device__ __forceinline__ void ldm_x4(uint32_t& d0, uint32_t& d1, uint32_t& d2, uint32_t& d3,
                                       uint32_t addr) {
    asm volatile("ldmatrix.sync.aligned.m8n8.x4.shared.b16 {%0,%1,%2,%3}, [%4];"
                 : "=r"(d0), "=r"(d1), "=r"(d2), "=r"(d3) : "r"(addr));
}
__device__ __forceinline__ void mma_bf16(float* c, const uint32_t* a, const uint32_t* b) {
    asm volatile("mma.sync.aligned.m16n8k16.row.col.f32.bf16.bf16.f32 "
                 "{%0,%1,%2,%3}, {%4,%5,%6,%7}, {%8,%9}, {%0,%1,%2,%3};"
                 : "+f"(c[0]), "+f"(c[1]), "+f"(c[2]), "+f"(c[3])
                 : "r"(a[0]), "r"(a[1]), "r"(a[2]), "r"(a[3]), "r"(b[0]), "r"(b[1]));
}
__device__ __forceinline__ void fma2(float2& d, const float2& a, const float2& b) {
    unsigned long long dd = *reinterpret_cast<const unsigned long long*>(&d);
    unsigned long long aa = *reinterpret_cast<const unsigned long long*>(&a);
    unsigned long long bb = *reinterpret_cast<const unsigned long long*>(&b);
    asm("fma.rn.f32x2 %0, %1, %2, %0;" : "+l"(dd) : "l"(aa), "l"(bb));
    d = *reinterpret_cast<float2*>(&dd);
}
__device__ __forceinline__ float sigm(float x) { return 1.f / (1.f + __expf(-x)); }
__device__ __forceinline__ void split_bf16(float v, __nv_bfloat16& h, __nv_bfloat16& l) {
    h = __float2bfloat16_rn(v);
    l = __float2bfloat16_rn(v - __bfloat162float(h));
}

// ============================================================
// Kernel 1a: W_rec = W_ih[:,4096:] + W_hh, bias, flags
// ============================================================
__global__ void prep_kernel(const float* __restrict__ W_ih, const float* __restrict__ W_hh,
                            const float* __restrict__ b_ih, const float* __restrict__ b_hh) {
    int idx = blockIdx.x * blockDim.x + threadIdx.x;
    if (idx < G4 * H) {
        int r = idx >> 10, j = idx & 1023;
        g_Wrec[idx] = W_ih[(size_t)r * FIVEH + KIN + j] + W_hh[idx];
    }
    if (idx < G4) g_bias[idx] = b_ih[idx] + b_hh[idx];
    if (idx < NBLK) g_flagw[idx] = 0;
}

// Kernel 1b: split W_ih[:, :4096] into bf16 hi/lo
__global__ void conv_w_kernel(const float* __restrict__ W_ih) {
    int idx = blockIdx.x * blockDim.x + threadIdx.x;     // 16.7M
    int r = idx >> 12, c = idx & 4095;
    float v = W_ih[(size_t)r * FIVEH + c];
    __nv_bfloat16 h, l;
    split_bf16(v, h, l);
    g_W_hi[idx] = h; g_W_lo[idx] = l;
}

// Kernel 1c: split feats = concat(x, hi) into bf16 hi/lo
__global__ void conv_f_kernel(const float* __restrict__ x, const float* __restrict__ hi) {
    int idx = blockIdx.x * blockDim.x + threadIdx.x;     // 2M
    int r = idx >> 12, c = idx & 4095;
    float v = (c < 2048) ? x[(size_t)r * 2048 + c] : hi[(size_t)r * 2048 + (c - 2048)];
    __nv_bfloat16 h, l;
    split_bf16(v, h, l);
    g_F_hi[idx] = h; g_F_lo[idx] = l;
}

// ============================================================
// Kernel 2: bf16 HMMA GEMM, split 3-product (hi*hi + hi*lo + lo*hi)
// P[m][n] = feats[m]·W_ih[n] + bias[n];  BM=BN=128, BK=32
// ============================================================
#define BK       32
#define KTILES   (KIN / BK)          // 128
#define LDS_B    80                  // padded row stride in bytes (40 bf16)
#define T_AHI    0
#define T_ALO    10240
#define T_BHI    20480
#define T_BLO    30720
#define STAGE_B  40960
#define GSMEM    (2 * STAGE_B)       // 81920

__global__ __launch_bounds__(256, 1)
void gemm_hmma(float* __restrict__ dummy) {
    extern __shared__ char smem[];
    uint32_t sb = smem_u32(smem);
    int tid = threadIdx.x, lane = tid & 31, wid = tid >> 5;
    int warp_m = wid >> 2, warp_n = wid & 3;     // 2 x 4 warps
    int bn = blockIdx.x, bm = blockIdx.y;        // 32 x 4

    // ---- per-thread cp.async source/dest precompute ----
    // chunk c (0..2047): tile=c>>9, cc=c&511: row=cc>>2, seg=cc&3
    const char* gsrc[8];
    uint32_t    sdst[8];
#pragma unroll
    for (int j = 0; j < 8; j++) {
        int c = j * 256 + tid;
        int tile = c >> 9, cc = c & 511, row = cc >> 2, seg = cc & 3;
        const __nv_bfloat16* base;
        int grow;
        if (tile == 0)      { base = g_F_hi; grow = bm * 128 + row; }
        else if (tile == 1) { base = g_F_lo; grow = bm * 128 + row; }
        else if (tile == 2) { base = g_W_hi; grow = bn * 128 + row; }
        else                { base = g_W_lo; grow = bn * 128 + row; }
        gsrc[j] = (const char*)(base + (size_t)grow * KIN + seg * 8);
        sdst[j] = sb + tile * 10240 + row * LDS_B + seg * 16;
    }

    // ---- ldmatrix per-thread base addresses ----
    int r8 = lane & 7, mi01 = (lane >> 3) & 1, kh = (lane >> 4) & 1;
    uint32_t aoff = (uint32_t)((warp_m * 64 + mi01 * 8 + r8) * LDS_B + kh * 16);
    uint32_t boff = (uint32_t)((warp_n * 32 + mi01 * 8 + r8) * LDS_B + kh * 16);

    float acc[4][4][4];
#pragma unroll
    for (int i = 0; i < 4; i++)
#pragma unroll
        for (int j = 0; j < 4; j++)
#pragma unroll
            for (int q = 0; q < 4; q++) acc[i][j][q] = 0.f;

    // prologue: stage 0
#pragma unroll
    for (int j = 0; j < 8; j++) CP_ASYNC16(sdst[j], gsrc[j]);
    CP_COMMIT();

    for (int kt = 0; kt < KTILES; kt++) {
        if (kt + 1 < KTILES) {
            uint32_t stoff = ((kt + 1) & 1) * STAGE_B;
            size_t goff = (size_t)(kt + 1) * BK * 2;   // bytes along k
#pragma unroll
            for (int j = 0; j < 8; j++) CP_ASYNC16(sdst[j] + stoff - (kt & 1 ? 0 : 0) + ((kt + 1) & 1 ? 0 : 0), gsrc[j] + goff);
            // note: sdst[j] already points into stage 0; add stage offset explicitly:
            CP_COMMIT();
            CP_WAIT(1);
        } else {
            CP_WAIT(0);
        }
        __syncthreads();

        uint32_t st = sb + (kt & 1) * STAGE_B;
#pragma unroll
        for (int ks = 0; ks < 2; ks++) {
            uint32_t ko = ks * 32;   // 16 bf16 = 32 bytes
            uint32_t ahi[4][4], alo[4][4], bhi[4][2], blo[4][2];
#pragma unroll
            for (int mt = 0; mt < 4; mt++) {
                uint32_t a = aoff + mt * (16 * LDS_B) + ko;
                ldm_x4(ahi[mt][0], ahi[mt][1], ahi[mt][2], ahi[mt][3], st + T_AHI - sb + sb + a); // st+T_AHI+a
                ldm_x4(alo[mt][0], alo[mt][1], alo[mt][2], alo[mt][3], st + T_ALO + a);
            }
#pragma unroll
            for (int g = 0; g < 2; g++) {
                uint32_t b = boff + g * (16 * LDS_B) + ko;
                uint32_t d0, d1, d2, d3;
                ldm_x4(d0, d1, d2, d3, st + T_BHI + b);
                bhi[g * 2][0] = d0; bhi[g * 2][1] = d2;
                bhi[g * 2 + 1][0] = d1; bhi[g * 2 + 1][1] = d3;
                ldm_x4(d0, d1, d2, d3, st + T_BLO + b);
                blo[g * 2][0] = d0; blo[g * 2][1] = d2;
                blo[g * 2 + 1][0] = d1; blo[g * 2 + 1][1] = d3;
            }
#pragma unroll
            for (int mt = 0; mt < 4; mt++)
#pragma unroll
                for (int nt = 0; nt < 4; nt++) {
                    mma_bf16(acc[mt][nt], ahi[mt], bhi[nt]);
                    mma_bf16(acc[mt][nt], ahi[mt], blo[nt]);
                    mma_bf16(acc[mt][nt], alo[mt], bhi[nt]);
                }
        }
        __syncthreads();
    }

    // ---- epilogue ----
    int gid = lane >> 2, tig = lane & 3;
#pragma unroll
    for (int mt = 0; mt < 4; mt++) {
        int row0 = bm * 128 + warp_m * 64 + mt * 16 + gid;
#pragma unroll
        for (int nt = 0; nt < 4; nt++) {
            int col = bn * 128 + warp_n * 32 + nt * 8 + tig * 2;
            float2 bias2 = *(const float2*)&g_bias[col];
            float2 v0 = make_float2(acc[mt][nt][0] + bias2.x, acc[mt][nt][1] + bias2.y);
            float2 v1 = make_float2(acc[mt][nt][2] + bias2.x, acc[mt][nt][3] + bias2.y);
            *(float2*)&g_P[(size_t)row0 * G4 + col] = v0;
            *(float2*)&g_P[(size_t)(row0 + 8) * G4 + col] = v1;
        }
    }
    if (dummy) *dummy = 0.f;   // never taken; keeps signature future-proof
}

// ============================================================
// Kernel 3: persistent LSTM recurrence (release/acquire sync)
// ============================================================
__global__ __launch_bounds__(NTHR, 1) void lstm_kernel() {
    __shared__ float h_sh[H];
    __shared__ float red[32][4];

    int tid = threadIdx.x, b = blockIdx.x;
    int w = tid >> 5, l = tid & 31;
    int rg = w >> 2, cc = w & 3;
    int jbase = b * 8;

    float2 wreg[4][4];
#pragma unroll
    for (int row = 0; row < 4; row++) {
        int rr = rg * 4 + row;
        int r = (rr >> 3) * 1024 + jbase + (rr & 7);
        const float2* wp = (const float2*)(g_Wrec + (size_t)r * H + cc * 256);
#pragma unroll
        for (int i = 0; i < 4; i++) wreg[row][i] = wp[i * 32 + l];
    }
    h_sh[tid] = 0.f;
    float c_reg = 0.f;
    int prow = (l >> 3) * 1024 + jbase + (l & 7);
    __syncthreads();

    for (int t = 0; t < L; t++) {
        float pval = 0.f;
        if (w == 0) pval = g_P[(size_t)t * G4 + prow];

        float2 acc[4];
#pragma unroll
        for (int row = 0; row < 4; row++) acc[row] = make_float2(0.f, 0.f);
        const float2* h2 = (const float2*)h_sh;
#pragma unroll
        for (int i = 0; i < 4; i++) {
            float2 hv = h2[cc * 128 + i * 32 + l];
#pragma unroll
            for (int row = 0; row < 4; row++) fma2(acc[row], wreg[row][i], hv);
        }
        float accs[4];
#pragma unroll
        for (int row = 0; row < 4; row++) accs[row] = acc[row].x + acc[row].y;
#pragma unroll
        for (int off = 16; off; off >>= 1)
#pragma unroll
            for (int row = 0; row < 4; row++)
                accs[row] += __shfl_xor_sync(0xffffffffu, accs[row], off);
        if (l == 0) {
#pragma unroll
            for (int row = 0; row < 4; row++) red[rg * 4 + row][cc] = accs[row];
        }
        __syncthreads();

        if (w == 0) {
            float gate = pval + red[l][0] + red[l][1] + red[l][2] + red[l][3];
            float fg = __shfl_sync(0xffffffffu, gate, l + 8);
            float gg = __shfl_sync(0xffffffffu, gate, l + 16);
            float og = __shfl_sync(0xffffffffu, gate, l + 24);
            if (l < 8) {
                float cn = sigm(fg) * c_reg + sigm(gate) * tanhf(gg);
                float hn = sigm(og) * tanhf(cn);
                c_reg = cn;
                g_outs[(size_t)t * H + jbase + l] = hn;
                asm volatile("red.release.gpu.global.add.s32 [%0], 1;"
                             :: "l"(&g_flagw[b]) : "memory");
            }
        }

        if (t < L - 1) {
            if (tid < NBLK) {
                int target = 8 * (t + 1), v, spins = 0;
                for (;;) {
                    asm volatile("ld.acquire.gpu.global.s32 %0, [%1];"
                                 : "=r"(v) : "l"(&g_flagw[tid]) : "memory");
                    if (v >= target) break;
                    if (++spins > 4) asm volatile("nanosleep.u32 64;");
                }
            }
            __syncthreads();
            h_sh[tid] = __ldcg(&g_outs[(size_t)t * H + tid]);
            __syncthreads();
        }
    }
}

// ============================================================
// Kernel 4: FC — 8 timesteps per block for W_fc reuse
// ============================================================
__global__ __launch_bounds__(256) void fc_kernel(const float* __restrict__ W_fc,
                                                 const float* __restrict__ b_fc,
                                                 float* __restrict__ out) {
    int t0 = blockIdx.x * 8;
    __shared__ float hsh[8][H];
    for (int i = threadIdx.x; i < 8 * H; i += 256)
        hsh[i >> 10][i & 1023] = g_outs[(size_t)t0 * H + i];
    __syncthreads();
    int w = threadIdx.x >> 5, l = threadIdx.x & 31;
    for (int lab = w; lab < LABELS; lab += 8) {
        const float* wr = W_fc + (size_t)lab * H;
        float wv[32];
#pragma unroll
        for (int i = 0; i < 32; i++) wv[i] = wr[l + 32 * i];
        float s[8];
#pragma unroll
        for (int tt = 0; tt < 8; tt++) s[tt] = 0.f;
#pragma unroll
        for (int i = 0; i < 32; i++)
#pragma unroll
            for (int tt = 0; tt < 8; tt++) s[tt] += wv[i] * hsh[tt][l + 32 * i];
#pragma unroll
        for (int off = 16; off; off >>= 1)
#pragma unroll
            for (int tt = 0; tt < 8; tt++) s[tt] += __shfl_xor_sync(0xffffffffu, s[tt], off);
        if (l == 0) {
#pragma unroll
            for (int tt = 0; tt < 8; tt++)
                out[(size_t)(t0 + tt) * LABELS + lab] = s[tt] + b_fc[lab];
        }
    }
}

// ============================================================
extern "C" void kernel_launch(void* const* d_in, const int* in_sizes, int n_in,
                              void* d_out, int out_size) {
    const float* x    = (const float*)d_in[0];
    const float* hi   = (const float*)d_in[1];
    const float* W_ih = (const float*)d_in[2];
    const float* W_hh = (const float*)d_in[3];
    const float* b_ih = (const float*)d_in[4];
    const float* b_hh = (const float*)d_in[5];
    const float* W_fc = (const float*)d_in[6];
    const float* b_fc = (const float*)d_in[7];
    float* out = (float*)d_out;

    cudaFuncSetAttribute(gemm_hmma, cudaFuncAttributeMaxDynamicSharedMemorySize, GSMEM);

    prep_kernel<<<(G4 * H + 255) / 256, 256>>>(W_ih, W_hh, b_ih, b_hh);
    conv_w_kernel<<<(G4 * KIN) / 256, 256>>>(W_ih);
    conv_f_kernel<<<(L * KIN) / 256, 256>>>(x, hi);
    gemm_hmma<<<dim3(G4 / 128, L / 128), 256, GSMEM>>>(nullptr);
    lstm_kernel<<<NBLK, NTHR>>>();
    fc_kernel<<<L / 8, 256>>>(W_fc, b_fc, out);
}